// round 2
// baseline (speedup 1.0000x reference)
#include <cuda_runtime.h>

// ---------------- scratch (no allocations allowed) ----------------
__device__ __align__(16) float g_pool1[512 * 20 * 12 * 12]; // conv1 output pooled
__device__ __align__(16) float g_feats[512 * 640];          // conv2 output pooled (flattened)
__device__ __align__(16) float g_M[512 * 1024];             // feats @ T^T
__device__ __align__(16) float g_close[2][512 * 64];        // MBD closeness partials (j-halves)

// ================= Kernel 1: conv1 (1->20, 5x5) + relu + maxpool2 =================
// in: x[512][1][28][28], out: g_pool1[b][oc][12][12]
__global__ __launch_bounds__(256) void conv1_kernel(const float* __restrict__ x,
                                                    const float* __restrict__ w,
                                                    const float* __restrict__ bias) {
    __shared__ __align__(16) float sx[784];
    __shared__ float sw[500];
    __shared__ float sb[20];
    const int b = blockIdx.x, tid = threadIdx.x;
    const float* xb = x + b * 784;
    for (int i = tid; i < 784; i += 256) sx[i] = xb[i];
    for (int i = tid; i < 500; i += 256) sw[i] = w[i];
    if (tid < 20) sb[tid] = bias[tid];
    __syncthreads();

    for (int o = tid; o < 2880; o += 256) {
        const int oc = o / 144, p = o % 144;
        const int oy = p / 12, ox = p % 12;
        const int r0 = oy * 2, c0 = ox * 2;
        float win[6][6];
#pragma unroll
        for (int r = 0; r < 6; r++) {
#pragma unroll
            for (int c = 0; c < 3; c++) {
                float2 v = *(const float2*)&sx[(r0 + r) * 28 + c0 + c * 2];
                win[r][c * 2] = v.x; win[r][c * 2 + 1] = v.y;
            }
        }
        float a00 = 0.f, a01 = 0.f, a10 = 0.f, a11 = 0.f;
        const float* wp = &sw[oc * 25];
#pragma unroll
        for (int ky = 0; ky < 5; ky++)
#pragma unroll
            for (int kx = 0; kx < 5; kx++) {
                const float wv = wp[ky * 5 + kx];
                a00 += wv * win[ky][kx];     a01 += wv * win[ky][kx + 1];
                a10 += wv * win[ky + 1][kx]; a11 += wv * win[ky + 1][kx + 1];
            }
        float m = fmaxf(fmaxf(a00, a01), fmaxf(a10, a11));
        g_pool1[b * 2880 + o] = fmaxf(m + sb[oc], 0.f);
    }
}

// ================= Kernel 2: conv2 (20->40, 5x5) + relu + maxpool2 =================
// in: g_pool1[b][20][12][12], out: g_feats[b][oc*16 + oy*4 + ox]
// 320 threads: g = tid/16 (0..19) handles oc = {g, g+20}; p = tid%16 is pool position.
// Per-ic weights (40*25 floats) double-buffered through smem.
__global__ __launch_bounds__(320) void conv2_kernel(const float* __restrict__ w,
                                                    const float* __restrict__ bias) {
    __shared__ __align__(16) float s_in[2880];
    __shared__ float swb[2][1000];
    __shared__ float sb[40];
    const int b = blockIdx.x, tid = threadIdx.x;
    for (int i = tid; i < 2880; i += 320) s_in[i] = g_pool1[b * 2880 + i];
    if (tid < 40) sb[tid] = bias[tid];
    for (int i = tid; i < 1000; i += 320) {
        const int oc = i / 25, t = i % 25;
        swb[0][i] = w[oc * 500 + t]; // ic = 0
    }
    __syncthreads();

    const int g = tid / 16;
    const int p = tid % 16;
    const int oy = p / 4, ox = p % 4;
    const int r0 = oy * 2, c0 = ox * 2;
    float a0[4] = {0.f, 0.f, 0.f, 0.f};
    float a1[4] = {0.f, 0.f, 0.f, 0.f};

    for (int ic = 0; ic < 20; ic++) {
        const int cur = ic & 1, nxt = cur ^ 1;
        if (ic < 19) {
            for (int i = tid; i < 1000; i += 320) {
                const int oc = i / 25, t = i % 25;
                swb[nxt][i] = w[oc * 500 + (ic + 1) * 25 + t];
            }
        }
        const float* ip = &s_in[ic * 144];
        float win[6][6];
#pragma unroll
        for (int r = 0; r < 6; r++)
#pragma unroll
            for (int c = 0; c < 3; c++) {
                float2 v = *(const float2*)&ip[(r0 + r) * 12 + c0 + c * 2];
                win[r][2 * c] = v.x; win[r][2 * c + 1] = v.y;
            }
        const float* w0 = &swb[cur][g * 25];
        const float* w1 = &swb[cur][(g + 20) * 25];
#pragma unroll
        for (int ky = 0; ky < 5; ky++)
#pragma unroll
            for (int kx = 0; kx < 5; kx++) {
                const float v00 = win[ky][kx],     v01 = win[ky][kx + 1];
                const float v10 = win[ky + 1][kx], v11 = win[ky + 1][kx + 1];
                const float wa = w0[ky * 5 + kx], wb = w1[ky * 5 + kx];
                a0[0] += wa * v00; a0[1] += wa * v01; a0[2] += wa * v10; a0[3] += wa * v11;
                a1[0] += wb * v00; a1[1] += wb * v01; a1[2] += wb * v10; a1[3] += wb * v11;
            }
        __syncthreads();
    }
    float m0 = fmaxf(fmaxf(a0[0], a0[1]), fmaxf(a0[2], a0[3]));
    g_feats[b * 640 + g * 16 + p] = fmaxf(m0 + sb[g], 0.f);
    float m1 = fmaxf(fmaxf(a1[0], a1[1]), fmaxf(a1[2], a1[3]));
    g_feats[b * 640 + (g + 20) * 16 + p] = fmaxf(m1 + sb[g + 20], 0.f);
}

// ================= Kernel 3: M = feats[512,640] @ T^T  (T:[1024,640]) =================
// Tiled GEMM, BM=64 (i), BN=64 (r), BK=16, 256 threads, 4x4 microtile.
// Column mapping col = tx + 16*n keeps Bs reads conflict-free with 17-stride pad.
__global__ __launch_bounds__(256) void gemmT_kernel(const float* __restrict__ T) {
    __shared__ __align__(16) float As[64 * 16];
    __shared__ float Bs[64 * 17];
    const int tx = threadIdx.x & 15, ty = threadIdx.x >> 4;
    const int i0 = blockIdx.y * 64, j0 = blockIdx.x * 64;
    const int lrow = threadIdx.x >> 2, lkq = threadIdx.x & 3;
    float acc[4][4] = {};

    for (int k0 = 0; k0 < 640; k0 += 16) {
        __syncthreads();
        float4 va = *(const float4*)&g_feats[(i0 + lrow) * 640 + k0 + lkq * 4];
        *(float4*)&As[lrow * 16 + lkq * 4] = va;
        float4 vb = *(const float4*)&T[(j0 + lrow) * 640 + k0 + lkq * 4];
        Bs[lrow * 17 + lkq * 4 + 0] = vb.x;
        Bs[lrow * 17 + lkq * 4 + 1] = vb.y;
        Bs[lrow * 17 + lkq * 4 + 2] = vb.z;
        Bs[lrow * 17 + lkq * 4 + 3] = vb.w;
        __syncthreads();
#pragma unroll
        for (int kk = 0; kk < 16; kk++) {
            float a[4], bb[4];
#pragma unroll
            for (int m = 0; m < 4; m++) a[m] = As[(ty * 4 + m) * 16 + kk];
#pragma unroll
            for (int n = 0; n < 4; n++) bb[n] = Bs[(tx + 16 * n) * 17 + kk];
#pragma unroll
            for (int m = 0; m < 4; m++)
#pragma unroll
                for (int n = 0; n < 4; n++) acc[m][n] += a[m] * bb[n];
        }
    }
#pragma unroll
    for (int m = 0; m < 4; m++)
#pragma unroll
        for (int n = 0; n < 4; n++)
            g_M[(i0 + ty * 4 + m) * 1024 + j0 + tx + 16 * n] = acc[m][n];
}

// ================= Kernel 4: minibatch discrimination =================
// closeness[i,b] = sum_j exp(-sum_c |M[i,b,c]-M[j,b,c]|)
// grid (4 i-tiles of 128, 64 b-slots, 2 j-halves), 128 threads.
// Each j-half writes its own partial buffer (deterministic, no atomics);
// fc_kernel sums the two halves. Doubles warp count vs single-pass.
__global__ __launch_bounds__(128) void mbd_kernel() {
    __shared__ __align__(16) float sj[128 * 16];
    const int bslot = blockIdx.y;
    const int half = blockIdx.z;
    const int i = blockIdx.x * 128 + threadIdx.x;
    float a[16];
    const float* mp = &g_M[i * 1024 + bslot * 16];
#pragma unroll
    for (int q = 0; q < 4; q++) {
        float4 v = *(const float4*)&mp[q * 4];
        a[q * 4] = v.x; a[q * 4 + 1] = v.y; a[q * 4 + 2] = v.z; a[q * 4 + 3] = v.w;
    }
    float acc = 0.f;
    const int jbase = half * 256;
    for (int j0 = jbase; j0 < jbase + 256; j0 += 128) {
        __syncthreads();
#pragma unroll
        for (int t = 0; t < 4; t++) {
            const int v = threadIdx.x + t * 128;     // 0..511 vec4 slots
            const int row = v >> 2, cq = v & 3;
            *(float4*)&sj[row * 16 + cq * 4] =
                *(const float4*)&g_M[(j0 + row) * 1024 + bslot * 16 + cq * 4];
        }
        __syncthreads();
#pragma unroll 4
        for (int jj = 0; jj < 128; jj++) {
            const float* r = &sj[jj * 16];
            float d = 0.f;
#pragma unroll
            for (int c = 0; c < 16; c++) d += fabsf(a[c] - r[c]);
            acc += __expf(-d);
        }
    }
    g_close[half][i * 64 + bslot] = acc;
}

// ================= Kernel 5: fc1 (704->100) + relu + fc2 (100->1) + sigmoid =============
// 8 images per block, 128 threads. Inputs transposed in smem [c][img]; fc1_w staged
// in 32-wide chunks (stride-33 pad -> conflict-free). Closeness = sum of 2 partials.
__global__ __launch_bounds__(128) void fc_kernel(const float* __restrict__ w1,
                                                 const float* __restrict__ b1,
                                                 const float* __restrict__ w2,
                                                 const float* __restrict__ b2,
                                                 float* __restrict__ out) {
    __shared__ __align__(16) float sin_t[704 * 8];
    __shared__ float wtile[100 * 33];
    __shared__ float shid[100 * 8];
    const int b0 = blockIdx.x * 8;
    const int tid = threadIdx.x;

    for (int idx = tid; idx < 704 * 8; idx += 128) {
        const int c = idx >> 3, img = idx & 7;
        float v;
        if (c < 640) {
            v = g_feats[(b0 + img) * 640 + c];
        } else {
            const int cc = (b0 + img) * 64 + (c - 640);
            v = g_close[0][cc] + g_close[1][cc];
        }
        sin_t[c * 8 + img] = v;
    }

    float acc[8];
    const int k = tid;
    if (k < 100) {
        const float bb = b1[k];
#pragma unroll
        for (int m = 0; m < 8; m++) acc[m] = bb;
    }
    for (int c0 = 0; c0 < 704; c0 += 32) {
        __syncthreads();
        for (int idx = tid; idx < 3200; idx += 128) {
            const int kk = idx >> 5, cc = idx & 31;
            wtile[kk * 33 + cc] = w1[kk * 704 + c0 + cc];
        }
        __syncthreads();
        if (k < 100) {
#pragma unroll 8
            for (int cc = 0; cc < 32; cc++) {
                const float wv = wtile[k * 33 + cc];
                const float* ip = &sin_t[(c0 + cc) * 8];
#pragma unroll
                for (int m = 0; m < 8; m++) acc[m] += wv * ip[m];
            }
        }
    }
    if (k < 100) {
#pragma unroll
        for (int m = 0; m < 8; m++) shid[k * 8 + m] = fmaxf(acc[m], 0.f);
    }
    __syncthreads();

    const int img = tid >> 4, part = tid & 15;
    float s = 0.f;
    for (int kk = part; kk < 100; kk += 16) s += shid[kk * 8 + img] * w2[kk];
#pragma unroll
    for (int off = 8; off; off >>= 1) s += __shfl_down_sync(0xffffffffu, s, off, 16);
    if (part == 0) {
        const float z = s + b2[0];
        out[b0 + img] = 1.f / (1.f + __expf(-z));
    }
}

// ================= launch =================
extern "C" void kernel_launch(void* const* d_in, const int* in_sizes, int n_in,
                              void* d_out, int out_size) {
    const float* x     = (const float*)d_in[0];
    const float* c1w   = (const float*)d_in[1];
    const float* c1b   = (const float*)d_in[2];
    const float* c2w   = (const float*)d_in[3];
    const float* c2b   = (const float*)d_in[4];
    const float* Tm    = (const float*)d_in[5];
    const float* fc1w  = (const float*)d_in[6];
    const float* fc1b  = (const float*)d_in[7];
    const float* fc2w  = (const float*)d_in[8];
    const float* fc2b  = (const float*)d_in[9];
    float* out = (float*)d_out;

    conv1_kernel<<<512, 256>>>(x, c1w, c1b);
    conv2_kernel<<<512, 320>>>(c2w, c2b);
    gemmT_kernel<<<dim3(16, 8), 256>>>(Tm);
    mbd_kernel<<<dim3(4, 64, 2), 128>>>();
    fc_kernel<<<64, 128>>>(fc1w, fc1b, fc2w, fc2b, out);
}